// round 4
// baseline (speedup 1.0000x reference)
#include <cuda_runtime.h>

// LSR_tensor_dot: out[b] = sum_ijk x[b,i,j,k] * T[i,j,k]
// T[i,j,k] = sum_s sum_abc core[a,b,c] * U1_s[i,a] * U2_s[j,b] * U3_s[k,c]
//
// Stage 1: W[s,a,b,k]   = sum_c core[a,b,c] * U3_s[k,c]
// Stage 2: C23[s,a,j,k] = sum_b W[s,a,b,k]  * U2_s[j,b]
// Stage 3: T[i,j,k]     = sum_s sum_a U1_s[i,a] * C23[s,a,j,k]
// Stage 4: out[b]       = dot(x[b,:], T)   <-- 512 MiB HBM read, the whole cost

#define I_DIM 64
#define R_DIM 8
#define SEP_N 4
#define TVOL (I_DIM * I_DIM * I_DIM)   // 262144

// Scratch in device globals (no allocation allowed in kernel_launch).
__device__ float g_W[SEP_N * R_DIM * R_DIM * I_DIM];      // 16384
__device__ float g_C23[SEP_N * R_DIM * I_DIM * I_DIM];    // 131072
__device__ float g_T[TVOL];                               // 262144

// factors layout: [s][mode][i][r] -> ((s*3 + mode)*64 + i)*8 + r

__global__ void lsr_stage1(const float* __restrict__ core,
                           const float* __restrict__ factors) {
    int idx = blockIdx.x * blockDim.x + threadIdx.x;      // SEP*R*R*I = 16384
    if (idx >= SEP_N * R_DIM * R_DIM * I_DIM) return;
    int k = idx & (I_DIM - 1);
    int t = idx >> 6;
    int b = t & (R_DIM - 1); t >>= 3;
    int a = t & (R_DIM - 1); t >>= 3;
    int s = t;
    const float* u3 = factors + ((size_t)(s * 3 + 2) * I_DIM + k) * R_DIM;
    const float* c  = core + (a * R_DIM + b) * R_DIM;
    float acc = 0.f;
    #pragma unroll
    for (int cc = 0; cc < R_DIM; cc++) acc = fmaf(c[cc], u3[cc], acc);
    g_W[idx] = acc;   // idx == ((s*R + a)*R + b)*I + k
}

__global__ void lsr_stage2(const float* __restrict__ factors) {
    int idx = blockIdx.x * blockDim.x + threadIdx.x;      // SEP*R*I*I = 131072
    if (idx >= SEP_N * R_DIM * I_DIM * I_DIM) return;
    int k = idx & 63;
    int j = (idx >> 6) & 63;
    int a = (idx >> 12) & 7;
    int s = idx >> 15;
    const float* u2 = factors + ((size_t)(s * 3 + 1) * I_DIM + j) * R_DIM;
    const float* w  = g_W + ((s * R_DIM + a) * R_DIM) * I_DIM + k; // stride I per b
    float acc = 0.f;
    #pragma unroll
    for (int b = 0; b < R_DIM; b++) acc = fmaf(u2[b], w[b * I_DIM], acc);
    g_C23[idx] = acc; // idx == ((s*R + a)*I + j)*I + k
}

__global__ void lsr_stage3(const float* __restrict__ factors) {
    int idx = blockIdx.x * blockDim.x + threadIdx.x;      // TVOL = 262144
    if (idx >= TVOL) return;
    int k = idx & 63;
    int j = (idx >> 6) & 63;
    int i = idx >> 12;
    float acc = 0.f;
    #pragma unroll
    for (int s = 0; s < SEP_N; s++) {
        const float* u1 = factors + ((size_t)(s * 3 + 0) * I_DIM + i) * R_DIM;
        const float* c23 = g_C23 + ((size_t)s * R_DIM * I_DIM + j) * I_DIM + k;
        #pragma unroll
        for (int a = 0; a < R_DIM; a++)
            acc = fmaf(u1[a], c23[(size_t)a * I_DIM * I_DIM], acc);
    }
    g_T[idx] = acc;
}

// One block per batch element b. 256 threads, float4 coalesced streams of
// x[b,:] (HBM) and T (L2-resident after first wave).
__global__ void __launch_bounds__(256) lsr_dot(const float* __restrict__ x,
                                               float* __restrict__ out) {
    const int b   = blockIdx.x;
    const int tid = threadIdx.x;
    const float4* __restrict__ xv = (const float4*)(x + (size_t)b * TVOL);
    const float4* __restrict__ tv = (const float4*)g_T;

    // 65536 float4 per batch element; 256 threads -> 256 iters, 2-way streams.
    float acc0 = 0.f, acc1 = 0.f;
    #pragma unroll 4
    for (int i = tid; i < TVOL / 4; i += 2 * 256) {
        float4 xa = xv[i];
        float4 ta = tv[i];
        acc0 = fmaf(xa.x, ta.x, acc0);
        acc0 = fmaf(xa.y, ta.y, acc0);
        acc0 = fmaf(xa.z, ta.z, acc0);
        acc0 = fmaf(xa.w, ta.w, acc0);
        float4 xb = xv[i + 256];
        float4 tb = tv[i + 256];
        acc1 = fmaf(xb.x, tb.x, acc1);
        acc1 = fmaf(xb.y, tb.y, acc1);
        acc1 = fmaf(xb.z, tb.z, acc1);
        acc1 = fmaf(xb.w, tb.w, acc1);
    }
    float acc = acc0 + acc1;

    // Warp reduce
    #pragma unroll
    for (int off = 16; off > 0; off >>= 1)
        acc += __shfl_down_sync(0xffffffffu, acc, off);

    __shared__ float sbuf[8];
    if ((tid & 31) == 0) sbuf[tid >> 5] = acc;
    __syncthreads();
    if (tid < 8) {
        float v = sbuf[tid];
        #pragma unroll
        for (int off = 4; off > 0; off >>= 1)
            v += __shfl_down_sync(0xffu, v, off);
        if (tid == 0) out[b] = v;
    }
}

extern "C" void kernel_launch(void* const* d_in, const int* in_sizes, int n_in,
                              void* d_out, int out_size) {
    const float* x       = (const float*)d_in[0];  // [512, 64,64,64]
    const float* core    = (const float*)d_in[1];  // [8,8,8]
    const float* factors = (const float*)d_in[2];  // [4,3,64,8]
    float* out = (float*)d_out;                    // [512]

    (void)in_sizes; (void)n_in; (void)out_size;

    lsr_stage1<<<(SEP_N * R_DIM * R_DIM * I_DIM + 255) / 256, 256>>>(core, factors);
    lsr_stage2<<<(SEP_N * R_DIM * I_DIM * I_DIM + 255) / 256, 256>>>(factors);
    lsr_stage3<<<(TVOL + 255) / 256, 256>>>(factors);
    lsr_dot<<<512, 256>>>(x, out);
}

// round 5
// speedup vs baseline: 1.0684x; 1.0684x over previous
#include <cuda_runtime.h>

// LSR_tensor_dot: out[b] = sum_ijk x[b,i,j,k] * T[i,j,k]
// T[i,j,k] = sum_s sum_abc core[a,b,c] * U1_s[i,a] * U2_s[j,b] * U3_s[k,c]
//
// Kernel 1 (build_T, 64 blocks = one per i, all-in-smem per block):
//   coeff_s[b,c] = sum_a U1_s[i,a] * core[a,b,c]
//   D_s[j,c]     = sum_b coeff_s[b,c] * U2_s[j,b]
//   T[i,j,k]     = sum_s sum_c D_s[j,c] * U3_s[k,c]
// Kernel 2 (dot): out[b] = <x[b,:], T>  -- 512 MiB HBM stream, the whole cost.

#define I_DIM 64
#define R_DIM 8
#define SEP_N 4
#define TVOL (I_DIM * I_DIM * I_DIM)   // 262144

__device__ float g_T[TVOL];            // 1 MiB, L2-resident during dot

// factors layout: [s][mode][i][r] -> linear: s*1536 + mode*512 + i*8 + r

__global__ void __launch_bounds__(256) lsr_build_T(const float* __restrict__ core,
                                                   const float* __restrict__ factors) {
    const int i   = blockIdx.x;        // 0..63
    const int tid = threadIdx.x;       // 0..255

    __shared__ float s_core[512];              // [a*64 + b*8 + c]
    __shared__ float s_u1[SEP_N][R_DIM];       // row i of U1_s
    __shared__ float s_u2[SEP_N][512];         // [j*8 + b]
    __shared__ float s_u3[SEP_N][512];         // [k*8 + c]
    __shared__ float s_coeff[SEP_N][64];       // [b*8 + c]
    __shared__ float s_D[SEP_N][512];          // [j*8 + c]

    // ---- cooperative loads ----
    #pragma unroll
    for (int t = tid; t < 512; t += 256) s_core[t] = core[t];
    if (tid < SEP_N * R_DIM) {
        int s = tid >> 3, r = tid & 7;
        s_u1[s][r] = factors[s * 1536 + 0 * 512 + i * R_DIM + r];
    }
    #pragma unroll
    for (int t = tid; t < SEP_N * 512; t += 256) {
        int s = t >> 9, rem = t & 511;
        s_u2[s][rem] = factors[s * 1536 + 1 * 512 + rem];
        s_u3[s][rem] = factors[s * 1536 + 2 * 512 + rem];
    }
    __syncthreads();

    // ---- coeff: 256 entries, one per thread ----
    {
        int s = tid >> 6, b = (tid >> 3) & 7, c = tid & 7;
        float acc = 0.f;
        #pragma unroll
        for (int a = 0; a < R_DIM; a++)
            acc = fmaf(s_u1[s][a], s_core[a * 64 + b * 8 + c], acc);
        s_coeff[s][(b << 3) | c] = acc;
    }
    __syncthreads();

    // ---- D: 2048 entries ----
    #pragma unroll
    for (int t = tid; t < SEP_N * 512; t += 256) {
        int s = t >> 9, rem = t & 511;       // rem = j*8 + c
        int j = rem >> 3, c = rem & 7;
        float acc = 0.f;
        #pragma unroll
        for (int b = 0; b < R_DIM; b++)
            acc = fmaf(s_coeff[s][(b << 3) | c], s_u2[s][(j << 3) | b], acc);
        s_D[s][rem] = acc;
    }
    __syncthreads();

    // ---- T slice: 4096 entries, coalesced store ----
    #pragma unroll
    for (int t = tid; t < 4096; t += 256) {
        int j = t >> 6, k = t & 63;
        float acc = 0.f;
        #pragma unroll
        for (int s = 0; s < SEP_N; s++)
            #pragma unroll
            for (int c = 0; c < R_DIM; c++)
                acc = fmaf(s_D[s][(j << 3) | c], s_u3[s][(k << 3) | c], acc);
        g_T[i * 4096 + t] = acc;
    }
}

// One block (512 threads) per batch element. 4 independent float4 streams per
// thread for deep MLP; __ldcs on x (touch-once, don't pollute L2 — T stays hot).
__global__ void __launch_bounds__(512) lsr_dot(const float* __restrict__ x,
                                               float* __restrict__ out) {
    const int b   = blockIdx.x;
    const int tid = threadIdx.x;
    const float4* __restrict__ xv = (const float4*)(x + (size_t)b * TVOL);
    const float4* __restrict__ tv = (const float4*)g_T;

    const int N4 = TVOL / 4;           // 65536
    float a0 = 0.f, a1 = 0.f, a2 = 0.f, a3 = 0.f;

    // 32 outer iterations, each issuing 8 independent float4 loads (4 x + 4 T).
    #pragma unroll 2
    for (int base = tid; base < N4; base += 4 * 512) {
        float4 x0 = __ldcs(xv + base);
        float4 x1 = __ldcs(xv + base + 512);
        float4 x2 = __ldcs(xv + base + 1024);
        float4 x3 = __ldcs(xv + base + 1536);
        float4 t0 = __ldg(tv + base);
        float4 t1 = __ldg(tv + base + 512);
        float4 t2 = __ldg(tv + base + 1024);
        float4 t3 = __ldg(tv + base + 1536);
        a0 = fmaf(x0.x, t0.x, a0); a0 = fmaf(x0.y, t0.y, a0);
        a0 = fmaf(x0.z, t0.z, a0); a0 = fmaf(x0.w, t0.w, a0);
        a1 = fmaf(x1.x, t1.x, a1); a1 = fmaf(x1.y, t1.y, a1);
        a1 = fmaf(x1.z, t1.z, a1); a1 = fmaf(x1.w, t1.w, a1);
        a2 = fmaf(x2.x, t2.x, a2); a2 = fmaf(x2.y, t2.y, a2);
        a2 = fmaf(x2.z, t2.z, a2); a2 = fmaf(x2.w, t2.w, a2);
        a3 = fmaf(x3.x, t3.x, a3); a3 = fmaf(x3.y, t3.y, a3);
        a3 = fmaf(x3.z, t3.z, a3); a3 = fmaf(x3.w, t3.w, a3);
    }
    float acc = (a0 + a1) + (a2 + a3);

    // warp reduce
    #pragma unroll
    for (int off = 16; off > 0; off >>= 1)
        acc += __shfl_down_sync(0xffffffffu, acc, off);

    __shared__ float sbuf[16];
    if ((tid & 31) == 0) sbuf[tid >> 5] = acc;
    __syncthreads();
    if (tid < 16) {
        float v = sbuf[tid];
        #pragma unroll
        for (int off = 8; off > 0; off >>= 1)
            v += __shfl_down_sync(0xffffu, v, off);
        if (tid == 0) out[b] = v;
    }
}

extern "C" void kernel_launch(void* const* d_in, const int* in_sizes, int n_in,
                              void* d_out, int out_size) {
    const float* x       = (const float*)d_in[0];  // [512, 64,64,64]
    const float* core    = (const float*)d_in[1];  // [8,8,8]
    const float* factors = (const float*)d_in[2];  // [4,3,64,8]
    float* out = (float*)d_out;                    // [512]

    (void)in_sizes; (void)n_in; (void)out_size;

    lsr_build_T<<<I_DIM, 256>>>(core, factors);
    lsr_dot<<<512, 512>>>(x, out);
}

// round 6
// speedup vs baseline: 1.1955x; 1.1190x over previous
#include <cuda_runtime.h>

// LSR_tensor_dot: out[b] = sum_ijk x[b,i,j,k] * T[i,j,k]
// T[i,j,k] = sum_s sum_abc core[a,b,c] * U1_s[i,a] * U2_s[j,b] * U3_s[k,c]
//
// Kernel 1 (build_T): one block per i, all contractions in smem; also zeros out[].
// Kernel 2 (dot): 1024 blocks (2 per batch row) x 256 thr, single full wave,
//                 atomicAdd partials. 512 MiB HBM stream = the whole cost.

#define I_DIM 64
#define R_DIM 8
#define SEP_N 4
#define TVOL (I_DIM * I_DIM * I_DIM)   // 262144 floats
#define N4   (TVOL / 4)                // 65536 float4 per row
#define HALF4 (N4 / 2)                 // 32768 float4 per block

__device__ float g_T[TVOL];            // 1 MiB, L2-resident during dot

// factors layout: [s][mode][i][r] -> linear: s*1536 + mode*512 + i*8 + r

__global__ void __launch_bounds__(256) lsr_build_T(const float* __restrict__ core,
                                                   const float* __restrict__ factors,
                                                   float* __restrict__ out) {
    const int i   = blockIdx.x;        // 0..63
    const int tid = threadIdx.x;       // 0..255

    // zero the output (d_out is poisoned; dot uses atomicAdd)
    if (tid < 8) out[i * 8 + tid] = 0.f;

    __shared__ float s_core[512];              // [a*64 + b*8 + c]
    __shared__ float s_u1[SEP_N][R_DIM];       // row i of U1_s
    __shared__ float s_u2[SEP_N][512];         // [j*8 + b]
    __shared__ float s_u3[SEP_N][512];         // [k*8 + c]
    __shared__ float s_coeff[SEP_N][64];       // [b*8 + c]
    __shared__ float s_D[SEP_N][512];          // [j*8 + c]

    #pragma unroll
    for (int t = tid; t < 512; t += 256) s_core[t] = core[t];
    if (tid < SEP_N * R_DIM) {
        int s = tid >> 3, r = tid & 7;
        s_u1[s][r] = factors[s * 1536 + 0 * 512 + i * R_DIM + r];
    }
    #pragma unroll
    for (int t = tid; t < SEP_N * 512; t += 256) {
        int s = t >> 9, rem = t & 511;
        s_u2[s][rem] = factors[s * 1536 + 1 * 512 + rem];
        s_u3[s][rem] = factors[s * 1536 + 2 * 512 + rem];
    }
    __syncthreads();

    {   // coeff: 256 entries, one per thread
        int s = tid >> 6, b = (tid >> 3) & 7, c = tid & 7;
        float acc = 0.f;
        #pragma unroll
        for (int a = 0; a < R_DIM; a++)
            acc = fmaf(s_u1[s][a], s_core[a * 64 + b * 8 + c], acc);
        s_coeff[s][(b << 3) | c] = acc;
    }
    __syncthreads();

    #pragma unroll
    for (int t = tid; t < SEP_N * 512; t += 256) {   // D: 2048 entries
        int s = t >> 9, rem = t & 511;               // rem = j*8 + c
        int j = rem >> 3, c = rem & 7;
        float acc = 0.f;
        #pragma unroll
        for (int b = 0; b < R_DIM; b++)
            acc = fmaf(s_coeff[s][(b << 3) | c], s_u2[s][(j << 3) | b], acc);
        s_D[s][rem] = acc;
    }
    __syncthreads();

    #pragma unroll
    for (int t = tid; t < 4096; t += 256) {          // T slice: 4096 entries
        int j = t >> 6, k = t & 63;
        float acc = 0.f;
        #pragma unroll
        for (int s = 0; s < SEP_N; s++)
            #pragma unroll
            for (int c = 0; c < R_DIM; c++)
                acc = fmaf(s_D[s][(j << 3) | c], s_u3[s][(k << 3) | c], acc);
        g_T[i * 4096 + t] = acc;
    }
}

// Two blocks per batch row: blockIdx = b*2 + seg. Lean 2-stream float4 loop
// (keeps regs <= 32 so 8 CTAs/SM fit -> 1024 blocks = ONE full wave).
__global__ void __launch_bounds__(256, 8) lsr_dot(const float* __restrict__ x,
                                                  float* __restrict__ out) {
    const int b   = blockIdx.x >> 1;
    const int seg = blockIdx.x & 1;
    const int tid = threadIdx.x;
    const float4* __restrict__ xv = (const float4*)(x + (size_t)b * TVOL) + seg * HALF4;
    const float4* __restrict__ tv = (const float4*)g_T + seg * HALF4;

    float a0 = 0.f, a1 = 0.f;
    // 32768 float4 per block; 2 independent streams, 64 pair-iterations.
    #pragma unroll 4
    for (int i = tid; i < HALF4; i += 2 * 256) {
        float4 xa = __ldcs(xv + i);
        float4 ta = __ldg(tv + i);
        float4 xb = __ldcs(xv + i + 256);
        float4 tb = __ldg(tv + i + 256);
        a0 = fmaf(xa.x, ta.x, a0); a0 = fmaf(xa.y, ta.y, a0);
        a0 = fmaf(xa.z, ta.z, a0); a0 = fmaf(xa.w, ta.w, a0);
        a1 = fmaf(xb.x, tb.x, a1); a1 = fmaf(xb.y, tb.y, a1);
        a1 = fmaf(xb.z, tb.z, a1); a1 = fmaf(xb.w, tb.w, a1);
    }
    float acc = a0 + a1;

    #pragma unroll
    for (int off = 16; off > 0; off >>= 1)
        acc += __shfl_down_sync(0xffffffffu, acc, off);

    __shared__ float sbuf[8];
    if ((tid & 31) == 0) sbuf[tid >> 5] = acc;
    __syncthreads();
    if (tid == 0) {
        float v = sbuf[0] + sbuf[1] + sbuf[2] + sbuf[3]
                + sbuf[4] + sbuf[5] + sbuf[6] + sbuf[7];
        atomicAdd(out + b, v);
    }
}

extern "C" void kernel_launch(void* const* d_in, const int* in_sizes, int n_in,
                              void* d_out, int out_size) {
    const float* x       = (const float*)d_in[0];  // [512, 64,64,64]
    const float* core    = (const float*)d_in[1];  // [8,8,8]
    const float* factors = (const float*)d_in[2];  // [4,3,64,8]
    float* out = (float*)d_out;                    // [512]

    (void)in_sizes; (void)n_in; (void)out_size;

    lsr_build_T<<<I_DIM, 256>>>(core, factors, out);
    lsr_dot<<<1024, 256>>>(x, out);
}

// round 8
// speedup vs baseline: 1.2177x; 1.0186x over previous
#include <cuda_runtime.h>

// LSR_tensor_dot: out[b] = sum_ijk x[b,i,j,k] * T[i,j,k]
// T[i,j,k] = sum_s sum_abc core[a,b,c] * U1_s[i,a] * U2_s[j,b] * U3_s[k,c]
//
// Kernel 1 (build_T): one block per i, all contractions in smem; zeros out[].
// Kernel 2 (dot): grid 1184 = 148 SMs x 8 CTAs -> ONE exactly-full wave.
//   Work = 8192 row-aligned units of 4096 float4 (16 KiB of x each), block p
//   takes units p, p+1184, ... One atomicAdd per unit. 512 MiB HBM stream.

#define I_DIM 64
#define R_DIM 8
#define SEP_N 4
#define TVOL   (I_DIM * I_DIM * I_DIM)   // 262144 floats
#define ROW4   (TVOL / 4)                // 65536 float4 per row
#define UNIT4  4096                      // float4 per unit
#define UPR    (ROW4 / UNIT4)            // 16 units per row
#define NUNIT  (512 * UPR)               // 8192 units
#define NBLK   1184                      // 148 SMs * 8 CTAs

__device__ float g_T[TVOL];              // 1 MiB, L2-resident during dot

// factors layout: [s][mode][i][r] -> linear: s*1536 + mode*512 + i*8 + r

__global__ void __launch_bounds__(256) lsr_build_T(const float* __restrict__ core,
                                                   const float* __restrict__ factors,
                                                   float* __restrict__ out) {
    const int i   = blockIdx.x;        // 0..63
    const int tid = threadIdx.x;       // 0..255

    if (tid < 8) out[i * 8 + tid] = 0.f;   // zero d_out (poisoned by harness)

    __shared__ float s_core[512];              // [a*64 + b*8 + c]
    __shared__ float s_u1[SEP_N][R_DIM];
    __shared__ float s_u2[SEP_N][512];         // [j*8 + b]
    __shared__ float s_u3[SEP_N][512];         // [k*8 + c]
    __shared__ float s_coeff[SEP_N][64];       // [b*8 + c]
    __shared__ float s_D[SEP_N][512];          // [j*8 + c]

    #pragma unroll
    for (int t = tid; t < 512; t += 256) s_core[t] = core[t];
    if (tid < SEP_N * R_DIM) {
        int s = tid >> 3, r = tid & 7;
        s_u1[s][r] = factors[s * 1536 + 0 * 512 + i * R_DIM + r];
    }
    #pragma unroll
    for (int t = tid; t < SEP_N * 512; t += 256) {
        int s = t >> 9, rem = t & 511;
        s_u2[s][rem] = factors[s * 1536 + 1 * 512 + rem];
        s_u3[s][rem] = factors[s * 1536 + 2 * 512 + rem];
    }
    __syncthreads();

    {   // coeff: 256 entries, one per thread
        int s = tid >> 6, b = (tid >> 3) & 7, c = tid & 7;
        float acc = 0.f;
        #pragma unroll
        for (int a = 0; a < R_DIM; a++)
            acc = fmaf(s_u1[s][a], s_core[a * 64 + b * 8 + c], acc);
        s_coeff[s][(b << 3) | c] = acc;
    }
    __syncthreads();

    #pragma unroll
    for (int t = tid; t < SEP_N * 512; t += 256) {   // D: 2048 entries
        int s = t >> 9, rem = t & 511;               // rem = j*8 + c
        int j = rem >> 3, c = rem & 7;
        float acc = 0.f;
        #pragma unroll
        for (int b = 0; b < R_DIM; b++)
            acc = fmaf(s_coeff[s][(b << 3) | c], s_u2[s][(j << 3) | b], acc);
        s_D[s][rem] = acc;
    }
    __syncthreads();

    #pragma unroll
    for (int t = tid; t < 4096; t += 256) {          // T slice: 4096 entries
        int j = t >> 6, k = t & 63;
        float acc = 0.f;
        #pragma unroll
        for (int s = 0; s < SEP_N; s++)
            #pragma unroll
            for (int c = 0; c < R_DIM; c++)
                acc = fmaf(s_D[s][(j << 3) | c], s_u3[s][(k << 3) | c], acc);
        g_T[i * 4096 + t] = acc;
    }
}

// grid 1184, block 256; each block strides over units p, p+1184, ...
__global__ void __launch_bounds__(256, 8) lsr_dot(const float* __restrict__ x,
                                                  float* __restrict__ out) {
    const int tid = threadIdx.x;
    const float4* __restrict__ tvb = (const float4*)g_T;
    __shared__ float sbuf[8];

    for (int u = blockIdx.x; u < NUNIT; u += NBLK) {
        const int row   = u >> 4;              // u / UPR
        const int chunk = u & (UPR - 1);
        const float4* __restrict__ xv =
            (const float4*)(x + (size_t)row * TVOL) + chunk * UNIT4;
        const float4* __restrict__ tv = tvb + chunk * UNIT4;

        float a0 = 0.f, a1 = 0.f;
        // 4096 float4 per unit: 8 pair-iterations of 2 independent streams.
        #pragma unroll
        for (int i = tid; i < UNIT4; i += 2 * 256) {
            float4 xa = __ldcs(xv + i);
            float4 ta = __ldg(tv + i);
            float4 xb = __ldcs(xv + i + 256);
            float4 tb = __ldg(tv + i + 256);
            a0 = fmaf(xa.x, ta.x, a0); a0 = fmaf(xa.y, ta.y, a0);
            a0 = fmaf(xa.z, ta.z, a0); a0 = fmaf(xa.w, ta.w, a0);
            a1 = fmaf(xb.x, tb.x, a1); a1 = fmaf(xb.y, tb.y, a1);
            a1 = fmaf(xb.z, tb.z, a1); a1 = fmaf(xb.w, tb.w, a1);
        }
        float acc = a0 + a1;

        #pragma unroll
        for (int off = 16; off > 0; off >>= 1)
            acc += __shfl_down_sync(0xffffffffu, acc, off);

        if ((tid & 31) == 0) sbuf[tid >> 5] = acc;
        __syncthreads();
        if (tid == 0) {
            float v = (sbuf[0] + sbuf[1]) + (sbuf[2] + sbuf[3])
                    + (sbuf[4] + sbuf[5]) + (sbuf[6] + sbuf[7]);
            atomicAdd(out + row, v);
        }
        __syncthreads();   // protect sbuf before next unit
    }
}

extern "C" void kernel_launch(void* const* d_in, const int* in_sizes, int n_in,
                              void* d_out, int out_size) {
    const float* x       = (const float*)d_in[0];  // [512, 64,64,64]
    const float* core    = (const float*)d_in[1];  // [8,8,8]
    const float* factors = (const float*)d_in[2];  // [4,3,64,8]
    float* out = (float*)d_out;                    // [512]

    (void)in_sizes; (void)n_in; (void)out_size;

    lsr_build_T<<<I_DIM, 256>>>(core, factors, out);
    lsr_dot<<<NBLK, 256>>>(x, out);
}